// round 1
// baseline (speedup 1.0000x reference)
#include <cuda_runtime.h>
#include <math.h>

#define MAXN 100000

// Scratch (allocation-free rule: device globals)
__device__ float g_M[(size_t)MAXN * 64];    // relu(x @ W_msg + b_msg)
__device__ float g_P[(size_t)MAXN * 64];    // x @ W_upd[0:64] + b_upd
__device__ float g_agg[(size_t)MAXN * 64];  // scatter-add destination
__device__ float g_deg[MAXN];               // in-degree (float)

// ---------------------------------------------------------------------------
// Zero agg + deg
// ---------------------------------------------------------------------------
__global__ void k_zero(int N)
{
    int i = blockIdx.x * blockDim.x + threadIdx.x;
    int tot = N * 64;
    if (i < tot) g_agg[i] = 0.f;
    if (i < N)   g_deg[i] = 0.f;
}

// ---------------------------------------------------------------------------
// out = act(X @ W + b), X:[N,64], W:[64,64] row-major, b:[64]
// mode 0 -> g_M with ReLU ; mode 1 -> g_P no ReLU
// Tiled: block = 256 threads, 64 rows per block, full K=64 in smem.
// ---------------------------------------------------------------------------
__global__ __launch_bounds__(256) void k_prep(const float* __restrict__ X,
                                              const float* __restrict__ W,
                                              const float* __restrict__ b,
                                              int N, int mode)
{
    __shared__ float xs[64][65];   // transposed x tile: xs[k][row]
    __shared__ float ws[64][64];   // W as-is: ws[k][col]

    int tid = threadIdx.x;
    int tx = tid & 15;             // col group
    int ty = tid >> 4;             // row group
    int rowBase = blockIdx.x << 6;

    // load W (4096 floats, float4)
    {
        const float4* Wv = (const float4*)W;
        float4* wsv = (float4*)ws;
        #pragma unroll
        for (int i = 0; i < 4; i++) wsv[tid + 256 * i] = Wv[tid + 256 * i];
    }
    // load x tile transposed
    {
        int r = tid >> 2, q = tid & 3;
        int grow = rowBase + r;
        const float4* xrow = (const float4*)(X + (size_t)grow * 64);
        #pragma unroll
        for (int j = 0; j < 4; j++) {
            int f = j * 4 + q;     // float4 index within row, 0..15
            float4 v = make_float4(0.f, 0.f, 0.f, 0.f);
            if (grow < N) v = xrow[f];
            xs[f * 4 + 0][r] = v.x;
            xs[f * 4 + 1][r] = v.y;
            xs[f * 4 + 2][r] = v.z;
            xs[f * 4 + 3][r] = v.w;
        }
    }
    __syncthreads();

    int c0 = tx * 4, r0 = ty * 4;
    float acc[4][4];
    #pragma unroll
    for (int i = 0; i < 4; i++)
        #pragma unroll
        for (int j = 0; j < 4; j++) acc[i][j] = 0.f;

    #pragma unroll
    for (int k = 0; k < 64; k++) {
        float4 bv = *(const float4*)&ws[k][c0];
        float a0 = xs[k][r0 + 0];
        float a1 = xs[k][r0 + 1];
        float a2 = xs[k][r0 + 2];
        float a3 = xs[k][r0 + 3];
        acc[0][0] += a0 * bv.x; acc[0][1] += a0 * bv.y; acc[0][2] += a0 * bv.z; acc[0][3] += a0 * bv.w;
        acc[1][0] += a1 * bv.x; acc[1][1] += a1 * bv.y; acc[1][2] += a1 * bv.z; acc[1][3] += a1 * bv.w;
        acc[2][0] += a2 * bv.x; acc[2][1] += a2 * bv.y; acc[2][2] += a2 * bv.z; acc[2][3] += a2 * bv.w;
        acc[3][0] += a3 * bv.x; acc[3][1] += a3 * bv.y; acc[3][2] += a3 * bv.z; acc[3][3] += a3 * bv.w;
    }

    float4 bb = *(const float4*)&b[c0];
    float* out = (mode == 0) ? g_M : g_P;
    #pragma unroll
    for (int i = 0; i < 4; i++) {
        int grow = rowBase + r0 + i;
        if (grow < N) {
            float4 v;
            v.x = acc[i][0] + bb.x;
            v.y = acc[i][1] + bb.y;
            v.z = acc[i][2] + bb.z;
            v.w = acc[i][3] + bb.w;
            if (mode == 0) {
                v.x = fmaxf(v.x, 0.f); v.y = fmaxf(v.y, 0.f);
                v.z = fmaxf(v.z, 0.f); v.w = fmaxf(v.w, 0.f);
            }
            *(float4*)(out + (size_t)grow * 64 + c0) = v;
        }
    }
}

// ---------------------------------------------------------------------------
// Edge scatter: 16 threads per edge; each thread moves one float4 of the
// 64-float message. agg[dst] += M[src] * w via vector reductions.
// ---------------------------------------------------------------------------
__global__ void k_scatter(const int* __restrict__ ei,
                          const float* __restrict__ ew, int E)
{
    int gid = blockIdx.x * blockDim.x + threadIdx.x;
    int e = gid >> 4;
    if (e >= E) return;
    int g = gid & 15;

    int src   = __ldg(ei + e);
    int dst   = __ldg(ei + E + e);
    float w   = __ldg(ew + e);

    float4 m = *(const float4*)(g_M + (size_t)src * 64 + g * 4);
    m.x *= w; m.y *= w; m.z *= w; m.w *= w;

    float* p = g_agg + (size_t)dst * 64 + g * 4;
    asm volatile("red.global.add.v4.f32 [%0], {%1, %2, %3, %4};"
                 :: "l"(p), "f"(m.x), "f"(m.y), "f"(m.z), "f"(m.w)
                 : "memory");

    if (g == 0) atomicAdd(g_deg + dst, 1.0f);
}

// ---------------------------------------------------------------------------
// Combine: h = relu(P + (agg/deg) @ W_upd[64:128]); L2-normalize rows; write out
// ---------------------------------------------------------------------------
__global__ __launch_bounds__(256) void k_combine(const float* __restrict__ Wupd,
                                                 float* __restrict__ out, int N)
{
    __shared__ float xs[64][65];
    __shared__ float ws[64][64];
    __shared__ float sums[64][17];

    int tid = threadIdx.x;
    int tx = tid & 15;
    int ty = tid >> 4;
    int rowBase = blockIdx.x << 6;

    // load W_upd rows 64..127
    {
        const float4* Wv = (const float4*)(Wupd + 64 * 64);
        float4* wsv = (float4*)ws;
        #pragma unroll
        for (int i = 0; i < 4; i++) wsv[tid + 256 * i] = Wv[tid + 256 * i];
    }
    // load agg tile transposed, scaled by 1/max(deg,1)
    {
        int r = tid >> 2, q = tid & 3;
        int grow = rowBase + r;
        float s = 0.f;
        if (grow < N) s = 1.0f / fmaxf(g_deg[grow], 1.0f);
        const float4* arow = (const float4*)(g_agg + (size_t)grow * 64);
        #pragma unroll
        for (int j = 0; j < 4; j++) {
            int f = j * 4 + q;
            float4 v = make_float4(0.f, 0.f, 0.f, 0.f);
            if (grow < N) v = arow[f];
            xs[f * 4 + 0][r] = v.x * s;
            xs[f * 4 + 1][r] = v.y * s;
            xs[f * 4 + 2][r] = v.z * s;
            xs[f * 4 + 3][r] = v.w * s;
        }
    }
    __syncthreads();

    int c0 = tx * 4, r0 = ty * 4;
    float acc[4][4];
    #pragma unroll
    for (int i = 0; i < 4; i++)
        #pragma unroll
        for (int j = 0; j < 4; j++) acc[i][j] = 0.f;

    #pragma unroll
    for (int k = 0; k < 64; k++) {
        float4 bv = *(const float4*)&ws[k][c0];
        float a0 = xs[k][r0 + 0];
        float a1 = xs[k][r0 + 1];
        float a2 = xs[k][r0 + 2];
        float a3 = xs[k][r0 + 3];
        acc[0][0] += a0 * bv.x; acc[0][1] += a0 * bv.y; acc[0][2] += a0 * bv.z; acc[0][3] += a0 * bv.w;
        acc[1][0] += a1 * bv.x; acc[1][1] += a1 * bv.y; acc[1][2] += a1 * bv.z; acc[1][3] += a1 * bv.w;
        acc[2][0] += a2 * bv.x; acc[2][1] += a2 * bv.y; acc[2][2] += a2 * bv.z; acc[2][3] += a2 * bv.w;
        acc[3][0] += a3 * bv.x; acc[3][1] += a3 * bv.y; acc[3][2] += a3 * bv.z; acc[3][3] += a3 * bv.w;
    }

    // epilogue: h = relu(acc + P), partial row sum-of-squares
    float h[4][4];
    #pragma unroll
    for (int i = 0; i < 4; i++) {
        int grow = rowBase + r0 + i;
        float4 pv = make_float4(0.f, 0.f, 0.f, 0.f);
        if (grow < N) pv = *(const float4*)(g_P + (size_t)grow * 64 + c0);
        h[i][0] = fmaxf(acc[i][0] + pv.x, 0.f);
        h[i][1] = fmaxf(acc[i][1] + pv.y, 0.f);
        h[i][2] = fmaxf(acc[i][2] + pv.z, 0.f);
        h[i][3] = fmaxf(acc[i][3] + pv.w, 0.f);
        sums[r0 + i][tx] = h[i][0] * h[i][0] + h[i][1] * h[i][1]
                         + h[i][2] * h[i][2] + h[i][3] * h[i][3];
    }
    __syncthreads();

    #pragma unroll
    for (int i = 0; i < 4; i++) {
        int grow = rowBase + r0 + i;
        if (grow < N) {
            float s = 0.f;
            #pragma unroll
            for (int t = 0; t < 16; t++) s += sums[r0 + i][t];
            float nrm = sqrtf(s);
            float sc = 1.0f / fmaxf(nrm, 1e-12f);
            float4 v;
            v.x = h[i][0] * sc; v.y = h[i][1] * sc;
            v.z = h[i][2] * sc; v.w = h[i][3] * sc;
            *(float4*)(out + (size_t)grow * 64 + c0) = v;
        }
    }
}

// ---------------------------------------------------------------------------
extern "C" void kernel_launch(void* const* d_in, const int* in_sizes, int n_in,
                              void* d_out, int out_size)
{
    const float* x    = (const float*)d_in[0];
    const int*   ei   = (const int*)  d_in[1];
    const float* ew   = (const float*)d_in[2];
    const float* Wmsg = (const float*)d_in[3];
    const float* bmsg = (const float*)d_in[4];
    const float* Wupd = (const float*)d_in[5];
    const float* bupd = (const float*)d_in[6];
    float* out = (float*)d_out;

    int N = in_sizes[0] / 64;
    int E = in_sizes[2];

    int tot = N * 64;
    k_zero<<<(tot + 255) / 256, 256>>>(N);

    int gb = (N + 63) / 64;
    k_prep<<<gb, 256>>>(x, Wmsg, bmsg, N, 0);
    k_prep<<<gb, 256>>>(x, Wupd, bupd, N, 1);

    long long sth = (long long)E * 16;
    int sblocks = (int)((sth + 255) / 256);
    k_scatter<<<sblocks, 256>>>(ei, ew, E);

    k_combine<<<gb, 256>>>(Wupd, out, N);
}

// round 2
// speedup vs baseline: 1.0450x; 1.0450x over previous
#include <cuda_runtime.h>
#include <cuda_fp16.h>
#include <math.h>

#define MAXN 100000

// Scratch (allocation-free rule: device globals)
__device__ __half g_Mh[(size_t)MAXN * 64];  // fp16 relu(x @ W_msg + b_msg)
__device__ float  g_agg[(size_t)MAXN * 64]; // scatter-add destination (f32)
__device__ float  g_deg[MAXN];              // in-degree

// ---------------------------------------------------------------------------
// Zero agg + deg (vectorized)
// ---------------------------------------------------------------------------
__global__ void k_zero(int N)
{
    int i = blockIdx.x * blockDim.x + threadIdx.x;
    int tot4 = N * 16;                // N*64 floats as float4
    if (i < tot4) ((float4*)g_agg)[i] = make_float4(0.f, 0.f, 0.f, 0.f);
    if (i < N)    g_deg[i] = 0.f;
}

// ---------------------------------------------------------------------------
// g_Mh = fp16( relu(X @ W_msg + b_msg) ), X:[N,64], W:[64,64] row-major
// block = 256 threads, 64 rows per block.
// ---------------------------------------------------------------------------
__global__ __launch_bounds__(256) void k_prep_m(const float* __restrict__ X,
                                                const float* __restrict__ W,
                                                const float* __restrict__ b,
                                                int N)
{
    __shared__ float xs[64][65];   // transposed x tile: xs[k][row]
    __shared__ float ws[64][64];   // W: ws[k][col]

    int tid = threadIdx.x;
    int tx = tid & 15;             // col group (4 cols)
    int ty = tid >> 4;             // row group (4 rows)
    int rowBase = blockIdx.x << 6;

    {
        const float4* Wv = (const float4*)W;
        float4* wsv = (float4*)ws;
        #pragma unroll
        for (int i = 0; i < 4; i++) wsv[tid + 256 * i] = Wv[tid + 256 * i];
    }
    {
        int r = tid >> 2, q = tid & 3;
        int grow = rowBase + r;
        const float4* xrow = (const float4*)(X + (size_t)grow * 64);
        #pragma unroll
        for (int j = 0; j < 4; j++) {
            int f = j * 4 + q;
            float4 v = make_float4(0.f, 0.f, 0.f, 0.f);
            if (grow < N) v = xrow[f];
            xs[f * 4 + 0][r] = v.x;
            xs[f * 4 + 1][r] = v.y;
            xs[f * 4 + 2][r] = v.z;
            xs[f * 4 + 3][r] = v.w;
        }
    }
    __syncthreads();

    int c0 = tx * 4, r0 = ty * 4;
    float acc[4][4];
    #pragma unroll
    for (int i = 0; i < 4; i++)
        #pragma unroll
        for (int j = 0; j < 4; j++) acc[i][j] = 0.f;

    #pragma unroll
    for (int k = 0; k < 64; k++) {
        float4 bv = *(const float4*)&ws[k][c0];
        float a0 = xs[k][r0 + 0];
        float a1 = xs[k][r0 + 1];
        float a2 = xs[k][r0 + 2];
        float a3 = xs[k][r0 + 3];
        acc[0][0] += a0 * bv.x; acc[0][1] += a0 * bv.y; acc[0][2] += a0 * bv.z; acc[0][3] += a0 * bv.w;
        acc[1][0] += a1 * bv.x; acc[1][1] += a1 * bv.y; acc[1][2] += a1 * bv.z; acc[1][3] += a1 * bv.w;
        acc[2][0] += a2 * bv.x; acc[2][1] += a2 * bv.y; acc[2][2] += a2 * bv.z; acc[2][3] += a2 * bv.w;
        acc[3][0] += a3 * bv.x; acc[3][1] += a3 * bv.y; acc[3][2] += a3 * bv.z; acc[3][3] += a3 * bv.w;
    }

    float4 bb = *(const float4*)&b[c0];
    #pragma unroll
    for (int i = 0; i < 4; i++) {
        int grow = rowBase + r0 + i;
        if (grow < N) {
            float v0 = fmaxf(acc[i][0] + bb.x, 0.f);
            float v1 = fmaxf(acc[i][1] + bb.y, 0.f);
            float v2 = fmaxf(acc[i][2] + bb.z, 0.f);
            float v3 = fmaxf(acc[i][3] + bb.w, 0.f);
            __half2 h01 = __floats2half2_rn(v0, v1);
            __half2 h23 = __floats2half2_rn(v2, v3);
            uint2 packed;
            packed.x = *(unsigned*)&h01;
            packed.y = *(unsigned*)&h23;
            *(uint2*)(g_Mh + (size_t)grow * 64 + c0) = packed;
        }
    }
}

// ---------------------------------------------------------------------------
// Edge scatter: 8 threads per edge, 2 edges per thread (e and e+Eh) for MLP.
// Each thread: 16B fp16 gather -> 8 floats -> 2x red.global.add.v4.f32
// ---------------------------------------------------------------------------
__device__ __forceinline__ void unpack_scale(uint4 r, float w, float out[8])
{
    __half2 h;
    float2 f;
    h = *(__half2*)&r.x; f = __half22float2(h); out[0] = f.x * w; out[1] = f.y * w;
    h = *(__half2*)&r.y; f = __half22float2(h); out[2] = f.x * w; out[3] = f.y * w;
    h = *(__half2*)&r.z; f = __half22float2(h); out[4] = f.x * w; out[5] = f.y * w;
    h = *(__half2*)&r.w; f = __half22float2(h); out[6] = f.x * w; out[7] = f.y * w;
}

__global__ void k_scatter(const int* __restrict__ ei,
                          const float* __restrict__ ew, int E, int Eh)
{
    int gid = blockIdx.x * blockDim.x + threadIdx.x;
    int e0 = gid >> 3;
    if (e0 >= Eh) return;
    int g = gid & 7;
    int e1 = e0 + Eh;
    bool has1 = (e1 < E);

    int   src0 = __ldg(ei + e0);
    int   dst0 = __ldg(ei + E + e0);
    float w0   = __ldg(ew + e0);
    int src1 = src0, dst1 = dst0;
    float w1 = 0.f;
    if (has1) {
        src1 = __ldg(ei + e1);
        dst1 = __ldg(ei + E + e1);
        w1   = __ldg(ew + e1);
    }

    // Two independent 16B gathers in flight
    uint4 r0 = *(const uint4*)(g_Mh + (size_t)src0 * 64 + g * 8);
    uint4 r1 = *(const uint4*)(g_Mh + (size_t)src1 * 64 + g * 8);

    float m0[8], m1[8];
    unpack_scale(r0, w0, m0);
    unpack_scale(r1, w1, m1);

    float* p0 = g_agg + (size_t)dst0 * 64 + g * 8;
    asm volatile("red.global.add.v4.f32 [%0], {%1, %2, %3, %4};"
                 :: "l"(p0), "f"(m0[0]), "f"(m0[1]), "f"(m0[2]), "f"(m0[3]) : "memory");
    asm volatile("red.global.add.v4.f32 [%0], {%1, %2, %3, %4};"
                 :: "l"(p0 + 4), "f"(m0[4]), "f"(m0[5]), "f"(m0[6]), "f"(m0[7]) : "memory");
    if (has1) {
        float* p1 = g_agg + (size_t)dst1 * 64 + g * 8;
        asm volatile("red.global.add.v4.f32 [%0], {%1, %2, %3, %4};"
                     :: "l"(p1), "f"(m1[0]), "f"(m1[1]), "f"(m1[2]), "f"(m1[3]) : "memory");
        asm volatile("red.global.add.v4.f32 [%0], {%1, %2, %3, %4};"
                     :: "l"(p1 + 4), "f"(m1[4]), "f"(m1[5]), "f"(m1[6]), "f"(m1[7]) : "memory");
    }

    if (g == 0) {
        atomicAdd(g_deg + dst0, 1.0f);
        if (has1) atomicAdd(g_deg + dst1, 1.0f);
    }
}

// ---------------------------------------------------------------------------
// Combine (fused K=128): h = relu([x || agg/deg] @ W_upd + b_upd), L2-normalize.
// ---------------------------------------------------------------------------
__global__ __launch_bounds__(256) void k_combine(const float* __restrict__ X,
                                                 const float* __restrict__ Wupd,
                                                 const float* __restrict__ b,
                                                 float* __restrict__ out, int N)
{
    __shared__ float xs[64][65];     // reused: x tile then agg tile
    __shared__ float ws[128][64];    // full W_upd
    __shared__ float sums[64][17];

    int tid = threadIdx.x;
    int tx = tid & 15;
    int ty = tid >> 4;
    int rowBase = blockIdx.x << 6;

    // load full W_upd (8192 floats = 2048 float4)
    {
        const float4* Wv = (const float4*)Wupd;
        float4* wsv = (float4*)ws;
        #pragma unroll
        for (int i = 0; i < 8; i++) wsv[tid + 256 * i] = Wv[tid + 256 * i];
    }
    // load x tile transposed
    {
        int r = tid >> 2, q = tid & 3;
        int grow = rowBase + r;
        const float4* xrow = (const float4*)(X + (size_t)grow * 64);
        #pragma unroll
        for (int j = 0; j < 4; j++) {
            int f = j * 4 + q;
            float4 v = make_float4(0.f, 0.f, 0.f, 0.f);
            if (grow < N) v = xrow[f];
            xs[f * 4 + 0][r] = v.x;
            xs[f * 4 + 1][r] = v.y;
            xs[f * 4 + 2][r] = v.z;
            xs[f * 4 + 3][r] = v.w;
        }
    }
    __syncthreads();

    int c0 = tx * 4, r0 = ty * 4;
    float acc[4][4];
    #pragma unroll
    for (int i = 0; i < 4; i++)
        #pragma unroll
        for (int j = 0; j < 4; j++) acc[i][j] = 0.f;

    // K half 1: x @ W_upd[0:64]
    #pragma unroll
    for (int k = 0; k < 64; k++) {
        float4 bv = *(const float4*)&ws[k][c0];
        float a0 = xs[k][r0 + 0];
        float a1 = xs[k][r0 + 1];
        float a2 = xs[k][r0 + 2];
        float a3 = xs[k][r0 + 3];
        acc[0][0] += a0 * bv.x; acc[0][1] += a0 * bv.y; acc[0][2] += a0 * bv.z; acc[0][3] += a0 * bv.w;
        acc[1][0] += a1 * bv.x; acc[1][1] += a1 * bv.y; acc[1][2] += a1 * bv.z; acc[1][3] += a1 * bv.w;
        acc[2][0] += a2 * bv.x; acc[2][1] += a2 * bv.y; acc[2][2] += a2 * bv.z; acc[2][3] += a2 * bv.w;
        acc[3][0] += a3 * bv.x; acc[3][1] += a3 * bv.y; acc[3][2] += a3 * bv.z; acc[3][3] += a3 * bv.w;
    }
    __syncthreads();

    // reload xs with agg/deg tile
    {
        int r = tid >> 2, q = tid & 3;
        int grow = rowBase + r;
        float s = 0.f;
        if (grow < N) s = 1.0f / fmaxf(g_deg[grow], 1.0f);
        const float4* arow = (const float4*)(g_agg + (size_t)grow * 64);
        #pragma unroll
        for (int j = 0; j < 4; j++) {
            int f = j * 4 + q;
            float4 v = make_float4(0.f, 0.f, 0.f, 0.f);
            if (grow < N) v = arow[f];
            xs[f * 4 + 0][r] = v.x * s;
            xs[f * 4 + 1][r] = v.y * s;
            xs[f * 4 + 2][r] = v.z * s;
            xs[f * 4 + 3][r] = v.w * s;
        }
    }
    __syncthreads();

    // K half 2: agg @ W_upd[64:128]
    #pragma unroll
    for (int k = 0; k < 64; k++) {
        float4 bv = *(const float4*)&ws[64 + k][c0];
        float a0 = xs[k][r0 + 0];
        float a1 = xs[k][r0 + 1];
        float a2 = xs[k][r0 + 2];
        float a3 = xs[k][r0 + 3];
        acc[0][0] += a0 * bv.x; acc[0][1] += a0 * bv.y; acc[0][2] += a0 * bv.z; acc[0][3] += a0 * bv.w;
        acc[1][0] += a1 * bv.x; acc[1][1] += a1 * bv.y; acc[1][2] += a1 * bv.z; acc[1][3] += a1 * bv.w;
        acc[2][0] += a2 * bv.x; acc[2][1] += a2 * bv.y; acc[2][2] += a2 * bv.z; acc[2][3] += a2 * bv.w;
        acc[3][0] += a3 * bv.x; acc[3][1] += a3 * bv.y; acc[3][2] += a3 * bv.z; acc[3][3] += a3 * bv.w;
    }

    // epilogue: +bias, relu, row sum-of-squares
    float4 bb = *(const float4*)&b[c0];
    float h[4][4];
    #pragma unroll
    for (int i = 0; i < 4; i++) {
        h[i][0] = fmaxf(acc[i][0] + bb.x, 0.f);
        h[i][1] = fmaxf(acc[i][1] + bb.y, 0.f);
        h[i][2] = fmaxf(acc[i][2] + bb.z, 0.f);
        h[i][3] = fmaxf(acc[i][3] + bb.w, 0.f);
        sums[r0 + i][tx] = h[i][0] * h[i][0] + h[i][1] * h[i][1]
                         + h[i][2] * h[i][2] + h[i][3] * h[i][3];
    }
    __syncthreads();

    #pragma unroll
    for (int i = 0; i < 4; i++) {
        int grow = rowBase + r0 + i;
        if (grow < N) {
            float s = 0.f;
            #pragma unroll
            for (int t = 0; t < 16; t++) s += sums[r0 + i][t];
            float nrm = sqrtf(s);
            float sc = 1.0f / fmaxf(nrm, 1e-12f);
            float4 v;
            v.x = h[i][0] * sc; v.y = h[i][1] * sc;
            v.z = h[i][2] * sc; v.w = h[i][3] * sc;
            *(float4*)(out + (size_t)grow * 64 + c0) = v;
        }
    }
}

// ---------------------------------------------------------------------------
extern "C" void kernel_launch(void* const* d_in, const int* in_sizes, int n_in,
                              void* d_out, int out_size)
{
    const float* x    = (const float*)d_in[0];
    const int*   ei   = (const int*)  d_in[1];
    const float* ew   = (const float*)d_in[2];
    const float* Wmsg = (const float*)d_in[3];
    const float* bmsg = (const float*)d_in[4];
    const float* Wupd = (const float*)d_in[5];
    const float* bupd = (const float*)d_in[6];
    float* out = (float*)d_out;

    int N = in_sizes[0] / 64;
    int E = in_sizes[2];

    int tot4 = N * 16;
    k_zero<<<(tot4 + 255) / 256, 256>>>(N);

    int gb = (N + 63) / 64;
    k_prep_m<<<gb, 256>>>(x, Wmsg, bmsg, N);

    int Eh = (E + 1) / 2;
    long long sth = (long long)Eh * 8;
    int sblocks = (int)((sth + 255) / 256);
    k_scatter<<<sblocks, 256>>>(ei, ew, E, Eh);

    k_combine<<<gb, 256>>>(x, Wupd, bupd, out, N);
}